// round 1
// baseline (speedup 1.0000x reference)
#include <cuda_runtime.h>
#include <cuda_bf16.h>
#include <math.h>

// Problem constants
#define BB 16
#define NN 1024
#define LL 313
#define NL 1337          // N + L
#define CC 768
#define HH 12
#define DH 64
#define MLPD 3072
#define LN_EPS 1e-5f

// ---------------------------------------------------------------------------
// Scratch (device globals; no runtime allocation allowed)
// ---------------------------------------------------------------------------
__device__ float g_xn    [(size_t)BB * NN * CC];   // ln1(x)
__device__ float g_tokens[(size_t)BB * NL * CC];   // [xn ; color_emb]
__device__ float g_q     [(size_t)BB * NN * CC];
__device__ float g_k     [(size_t)BB * NL * CC];
__device__ float g_v     [(size_t)BB * NL * CC];
__device__ float g_attn  [(size_t)BB * NN * CC];
__device__ float g_x1    [(size_t)BB * NN * CC];
__device__ float g_h     [(size_t)BB * NN * CC];
__device__ float g_mlp   [(size_t)BB * NN * MLPD];

// ---------------------------------------------------------------------------
// LayerNorm: one block (256 threads) per row of 768.
// writeTokens != 0 -> also scatter the normed row into g_tokens[b, n, :]
// ---------------------------------------------------------------------------
__global__ void ln_kernel(const float* __restrict__ in,
                          const float* __restrict__ gam,
                          const float* __restrict__ bet,
                          float* __restrict__ out,
                          int writeTokens) {
    int row = blockIdx.x;                       // b*N + n
    const float* xr = in + (size_t)row * CC;
    int tid = threadIdx.x;

    float v[3];
    float s1 = 0.f, s2 = 0.f;
#pragma unroll
    for (int i = 0; i < 3; ++i) {
        v[i] = xr[tid + 256 * i];
        s1 += v[i];
        s2 += v[i] * v[i];
    }
#pragma unroll
    for (int off = 16; off; off >>= 1) {
        s1 += __shfl_xor_sync(0xffffffffu, s1, off);
        s2 += __shfl_xor_sync(0xffffffffu, s2, off);
    }
    __shared__ float sm1[8], sm2[8];
    __shared__ float s_mu, s_rstd;
    int w = tid >> 5;
    if ((tid & 31) == 0) { sm1[w] = s1; sm2[w] = s2; }
    __syncthreads();
    if (tid == 0) {
        float a = 0.f, b2 = 0.f;
#pragma unroll
        for (int i = 0; i < 8; ++i) { a += sm1[i]; b2 += sm2[i]; }
        float mu = a * (1.0f / CC);
        float var = b2 * (1.0f / CC) - mu * mu;
        s_mu = mu;
        s_rstd = rsqrtf(var + LN_EPS);
    }
    __syncthreads();
    float mu = s_mu, rstd = s_rstd;

    float* orow = out + (size_t)row * CC;
    float* trow = nullptr;
    if (writeTokens) {
        int b = row / NN, n = row % NN;
        trow = g_tokens + ((size_t)b * NL + n) * CC;
    }
#pragma unroll
    for (int i = 0; i < 3; ++i) {
        int c = tid + 256 * i;
        float y = (v[i] - mu) * rstd * gam[c] + bet[c];
        orow[c] = y;
        if (writeTokens) trow[c] = y;
    }
}

// ---------------------------------------------------------------------------
// Copy color_emb into the tail of g_tokens
// ---------------------------------------------------------------------------
__global__ void copy_color_kernel(const float* __restrict__ ce) {
    int idx = blockIdx.x * blockDim.x + threadIdx.x;
    const int total = BB * LL * CC;
    if (idx < total) {
        int b = idx / (LL * CC);
        int r = idx % (LL * CC);
        g_tokens[((size_t)b * NL + NN) * CC + r] = ce[idx];
    }
}

// ---------------------------------------------------------------------------
// Tiled fp32 GEMM: Out[M,Nc] = A[M,K] @ W[K,Nc] + bias (+ epilogue)
// EPI: 0 = bias only, 1 = bias + residual, 2 = bias + exact GELU
// 64x64 tile, BK=16, 256 threads, 4x4 per-thread microtile.
// ---------------------------------------------------------------------------
template <int EPI>
__global__ void gemm_kernel(const float* __restrict__ A,
                            const float* __restrict__ W,
                            const float* __restrict__ bias,
                            const float* __restrict__ res,
                            float* __restrict__ Out,
                            int M, int K, int Nc) {
    __shared__ __align__(16) float As[16][68];   // [k][m]  (transposed A tile)
    __shared__ __align__(16) float Bs[16][68];   // [k][n]

    int tid = threadIdx.x;
    int tx = tid & 15, ty = tid >> 4;
    int rowBase = blockIdx.y * 64;
    int colBase = blockIdx.x * 64;

    float acc[4][4] = {};

    int kk = tid & 15;        // k within A tile
    int r0 = tid >> 4;        // row group within A tile
    int kr = tid >> 4;        // k row within B tile
    int c4 = (tid & 15) * 4;  // col within B tile

    for (int k0 = 0; k0 < K; k0 += 16) {
#pragma unroll
        for (int i = 0; i < 4; ++i) {
            int r = r0 + 16 * i;
            int row = rowBase + r;
            float vv = (row < M) ? A[(size_t)row * K + k0 + kk] : 0.f;
            As[kk][r] = vv;
        }
        float4 wv = *(const float4*)&W[(size_t)(k0 + kr) * Nc + colBase + c4];
        *(float4*)&Bs[kr][c4] = wv;
        __syncthreads();
#pragma unroll
        for (int k = 0; k < 16; ++k) {
            float4 a4 = *(const float4*)&As[k][ty * 4];
            float4 b4 = *(const float4*)&Bs[k][tx * 4];
            float av[4] = {a4.x, a4.y, a4.z, a4.w};
            float bv[4] = {b4.x, b4.y, b4.z, b4.w};
#pragma unroll
            for (int i = 0; i < 4; ++i)
#pragma unroll
                for (int j = 0; j < 4; ++j)
                    acc[i][j] += av[i] * bv[j];
        }
        __syncthreads();
    }

#pragma unroll
    for (int i = 0; i < 4; ++i) {
        int row = rowBase + ty * 4 + i;
        if (row >= M) continue;
#pragma unroll
        for (int j = 0; j < 4; ++j) {
            int col = colBase + tx * 4 + j;
            float v = acc[i][j] + bias[col];
            if (EPI == 1) v += res[(size_t)row * Nc + col];
            if (EPI == 2) v = 0.5f * v * (1.0f + erff(v * 0.70710678118654752f));
            Out[(size_t)row * Nc + col] = v;
        }
    }
}

// ---------------------------------------------------------------------------
// Flash attention (fp32, online softmax).
// Block: 256 threads (16x16). Grid: (N/64, H, B).
// Q tile = 64 queries x 64 dh; K/V chunk = 32 keys.
// Thread (ty,tx): scores 4 rows x 2 key-cols; output 4 rows x 4 dh-cols.
// ---------------------------------------------------------------------------
__global__ void attn_kernel(const int* __restrict__ mask) {
    int b = blockIdx.z, h = blockIdx.y, qt = blockIdx.x;

    __shared__ __align__(16) float Qt[64][68];   // [d][i]   (transposed)
    __shared__ __align__(16) float Kt[64][34];   // [d][j]   (transposed)
    __shared__ __align__(16) float Vs[32][68];   // [j][d]
    __shared__ __align__(16) float Ps[64][34];   // [i][j]

    int tid = threadIdx.x;
    int tx = tid & 15, ty = tid >> 4;
    int i0 = tid >> 4;
    int d4 = (tid & 15) * 4;

    const float* qbase = g_q + ((size_t)b * NN + qt * 64) * CC + h * DH;
#pragma unroll
    for (int rr = 0; rr < 4; ++rr) {
        int i = i0 + 16 * rr;
        float4 qv = *(const float4*)(qbase + (size_t)i * CC + d4);
        Qt[d4 + 0][i] = qv.x; Qt[d4 + 1][i] = qv.y;
        Qt[d4 + 2][i] = qv.z; Qt[d4 + 3][i] = qv.w;
    }

    float m[4], l[4], o[4][4];
#pragma unroll
    for (int r = 0; r < 4; ++r) {
        m[r] = -1e30f; l[r] = 0.f;
#pragma unroll
        for (int c = 0; c < 4; ++c) o[r][c] = 0.f;
    }

    const int*   mbase  = mask + ((size_t)b * NN + qt * 64) * NL;
    const float* kbase0 = g_k + (size_t)b * NL * CC + h * DH;
    const float* vbase0 = g_v + (size_t)b * NL * CC + h * DH;

    for (int kb = 0; kb < NL; kb += 32) {
        __syncthreads();   // protect Kt/Vs/Ps reuse
#pragma unroll
        for (int rr = 0; rr < 2; ++rr) {
            int j = i0 + 16 * rr;
            int krow = kb + j;
            float4 kv = {0.f, 0.f, 0.f, 0.f};
            float4 vv = {0.f, 0.f, 0.f, 0.f};
            if (krow < NL) {
                kv = *(const float4*)(kbase0 + (size_t)krow * CC + d4);
                vv = *(const float4*)(vbase0 + (size_t)krow * CC + d4);
            }
            Kt[d4 + 0][j] = kv.x; Kt[d4 + 1][j] = kv.y;
            Kt[d4 + 2][j] = kv.z; Kt[d4 + 3][j] = kv.w;
            *(float4*)&Vs[j][d4] = vv;
        }
        __syncthreads();

        float s[4][2] = {};
#pragma unroll 8
        for (int d = 0; d < 64; ++d) {
            float4 q4 = *(const float4*)&Qt[d][ty * 4];
            float2 k2 = *(const float2*)&Kt[d][tx * 2];
            s[0][0] += q4.x * k2.x; s[0][1] += q4.x * k2.y;
            s[1][0] += q4.y * k2.x; s[1][1] += q4.y * k2.y;
            s[2][0] += q4.z * k2.x; s[2][1] += q4.z * k2.y;
            s[3][0] += q4.w * k2.x; s[3][1] += q4.w * k2.y;
        }

#pragma unroll
        for (int r = 0; r < 4; ++r)
#pragma unroll
            for (int c = 0; c < 2; ++c) {
                int col = kb + tx * 2 + c;
                bool ok = (col < NL) &&
                          (mbase[(size_t)(ty * 4 + r) * NL + col] != 0);
                s[r][c] = ok ? s[r][c] * 0.125f : -INFINITY;
            }

#pragma unroll
        for (int r = 0; r < 4; ++r) {
            float cm = fmaxf(s[r][0], s[r][1]);
            cm = fmaxf(cm, __shfl_xor_sync(0xffffffffu, cm, 1));
            cm = fmaxf(cm, __shfl_xor_sync(0xffffffffu, cm, 2));
            cm = fmaxf(cm, __shfl_xor_sync(0xffffffffu, cm, 4));
            cm = fmaxf(cm, __shfl_xor_sync(0xffffffffu, cm, 8));
            float mn = fmaxf(m[r], cm);           // >= -1e30, always finite
            float alpha = __expf(m[r] - mn);
            float p0 = __expf(s[r][0] - mn);      // -inf -> 0
            float p1 = __expf(s[r][1] - mn);
            float rs = p0 + p1;
            rs += __shfl_xor_sync(0xffffffffu, rs, 1);
            rs += __shfl_xor_sync(0xffffffffu, rs, 2);
            rs += __shfl_xor_sync(0xffffffffu, rs, 4);
            rs += __shfl_xor_sync(0xffffffffu, rs, 8);
            l[r] = l[r] * alpha + rs;
            m[r] = mn;
            o[r][0] *= alpha; o[r][1] *= alpha; o[r][2] *= alpha; o[r][3] *= alpha;
            Ps[ty * 4 + r][tx * 2 + 0] = p0;
            Ps[ty * 4 + r][tx * 2 + 1] = p1;
        }
        __syncthreads();

#pragma unroll 4
        for (int j = 0; j < 32; ++j) {
            float4 vv = *(const float4*)&Vs[j][tx * 4];
#pragma unroll
            for (int r = 0; r < 4; ++r) {
                float p = Ps[ty * 4 + r][j];
                o[r][0] += p * vv.x; o[r][1] += p * vv.y;
                o[r][2] += p * vv.z; o[r][3] += p * vv.w;
            }
        }
    }

    float* obase = g_attn + ((size_t)b * NN + qt * 64) * CC + h * DH;
#pragma unroll
    for (int r = 0; r < 4; ++r) {
        float inv = 1.0f / l[r];
        float4 ov = {o[r][0] * inv, o[r][1] * inv, o[r][2] * inv, o[r][3] * inv};
        *(float4*)(obase + (size_t)(ty * 4 + r) * CC + tx * 4) = ov;
    }
}

// ---------------------------------------------------------------------------
// Launch
// ---------------------------------------------------------------------------
extern "C" void kernel_launch(void* const* d_in, const int* in_sizes, int n_in,
                              void* d_out, int out_size) {
    const float* x     = (const float*)d_in[0];
    const float* ce    = (const float*)d_in[1];
    const int*   mask  = (const int*)  d_in[2];
    const float* ln1_g = (const float*)d_in[3];
    const float* ln1_b = (const float*)d_in[4];
    const float* ln2_g = (const float*)d_in[5];
    const float* ln2_b = (const float*)d_in[6];
    const float* Wq = (const float*)d_in[7];
    const float* bq = (const float*)d_in[8];
    const float* Wk = (const float*)d_in[9];
    const float* bk = (const float*)d_in[10];
    const float* Wv = (const float*)d_in[11];
    const float* bv = (const float*)d_in[12];
    const float* Wp = (const float*)d_in[13];
    const float* bp = (const float*)d_in[14];
    const float* W1 = (const float*)d_in[15];
    const float* b1 = (const float*)d_in[16];
    const float* W2 = (const float*)d_in[17];
    const float* b2 = (const float*)d_in[18];
    float* out = (float*)d_out;

    float *p_xn, *p_tokens, *p_q, *p_k, *p_v, *p_attn, *p_x1, *p_h, *p_mlp;
    cudaGetSymbolAddress((void**)&p_xn,     g_xn);
    cudaGetSymbolAddress((void**)&p_tokens, g_tokens);
    cudaGetSymbolAddress((void**)&p_q,      g_q);
    cudaGetSymbolAddress((void**)&p_k,      g_k);
    cudaGetSymbolAddress((void**)&p_v,      g_v);
    cudaGetSymbolAddress((void**)&p_attn,   g_attn);
    cudaGetSymbolAddress((void**)&p_x1,     g_x1);
    cudaGetSymbolAddress((void**)&p_h,      g_h);
    cudaGetSymbolAddress((void**)&p_mlp,    g_mlp);

    const int Mq = BB * NN;     // 16384
    const int Mt = BB * NL;     // 21392

    // 1) LN1 -> xn (+ first part of tokens)
    ln_kernel<<<Mq, 256>>>(x, ln1_g, ln1_b, p_xn, 1);
    // 2) tokens tail <- color_emb
    {
        int total = BB * LL * CC;
        copy_color_kernel<<<(total + 255) / 256, 256>>>(ce);
    }
    // 3) Q = xn @ Wq + bq
    gemm_kernel<0><<<dim3(CC / 64, (Mq + 63) / 64), 256>>>(p_xn, Wq, bq, nullptr, p_q, Mq, CC, CC);
    // 4) K = tokens @ Wk + bk
    gemm_kernel<0><<<dim3(CC / 64, (Mt + 63) / 64), 256>>>(p_tokens, Wk, bk, nullptr, p_k, Mt, CC, CC);
    // 5) V = tokens @ Wv + bv
    gemm_kernel<0><<<dim3(CC / 64, (Mt + 63) / 64), 256>>>(p_tokens, Wv, bv, nullptr, p_v, Mt, CC, CC);
    // 6) flash attention -> g_attn
    attn_kernel<<<dim3(NN / 64, HH, BB), 256>>>(mask);
    // 7) x1 = xn + (attn @ Wp + bp)
    gemm_kernel<1><<<dim3(CC / 64, (Mq + 63) / 64), 256>>>(p_attn, Wp, bp, p_xn, p_x1, Mq, CC, CC);
    // 8) h = LN2(x1)
    ln_kernel<<<Mq, 256>>>(p_x1, ln2_g, ln2_b, p_h, 0);
    // 9) mlp = gelu(h @ W1 + b1)
    gemm_kernel<2><<<dim3(MLPD / 64, (Mq + 63) / 64), 256>>>(p_h, W1, b1, nullptr, p_mlp, Mq, CC, MLPD);
    // 10) out = x1 + (mlp @ W2 + b2)
    gemm_kernel<1><<<dim3(CC / 64, (Mq + 63) / 64), 256>>>(p_mlp, W2, b2, p_x1, out, Mq, MLPD, CC);
}

// round 3
// speedup vs baseline: 1.4102x; 1.4102x over previous
#include <cuda_runtime.h>
#include <cuda_bf16.h>
#include <math.h>
#include <stdint.h>

// Problem constants
#define BB 16
#define NN 1024
#define LL 313
#define NL 1337          // N + L
#define CC 768
#define HH 12
#define DH 64
#define MLPD 3072
#define LN_EPS 1e-5f

// ---------------------------------------------------------------------------
// Scratch (device globals; no runtime allocation allowed)
// ---------------------------------------------------------------------------
__device__ float g_xn    [(size_t)BB * NN * CC];   // ln1(x)
__device__ float g_tokens[(size_t)BB * NL * CC];   // [xn ; color_emb]
__device__ float g_q     [(size_t)BB * NN * CC];
__device__ float g_k     [(size_t)BB * NL * CC];
__device__ float g_v     [(size_t)BB * NL * CC];
__device__ float g_attn  [(size_t)BB * NN * CC];
__device__ float g_x1    [(size_t)BB * NN * CC];
__device__ float g_h     [(size_t)BB * NN * CC];
__device__ float g_mlp   [(size_t)BB * NN * MLPD];

// ---------------------------------------------------------------------------
// Helpers
// ---------------------------------------------------------------------------
__device__ __forceinline__ uint32_t smem_u32(const void* p) {
    uint32_t a;
    asm("{ .reg .u64 t; cvta.to.shared.u64 t, %1; cvt.u32.u64 %0, t; }" : "=r"(a) : "l"(p));
    return a;
}

#define CP_ASYNC16(saddr, gptr) \
    asm volatile("cp.async.cg.shared.global [%0], [%1], 16;" :: "r"(saddr), "l"(gptr))
#define CP_COMMIT() asm volatile("cp.async.commit_group;" ::: "memory")
#define CP_WAIT1()  asm volatile("cp.async.wait_group 1;" ::: "memory")
#define CP_WAIT0()  asm volatile("cp.async.wait_group 0;" ::: "memory")

// mma.sync m16n8k8 tf32: D += A*B  (A row-major 16x8, B col-major 8x8)
__device__ __forceinline__ void mma_tf32(float* d, const uint32_t* a, const uint32_t* b) {
    asm volatile(
        "mma.sync.aligned.m16n8k8.row.col.f32.tf32.tf32.f32 "
        "{%0,%1,%2,%3}, {%4,%5,%6,%7}, {%8,%9}, {%0,%1,%2,%3};"
        : "+f"(d[0]), "+f"(d[1]), "+f"(d[2]), "+f"(d[3])
        : "r"(a[0]), "r"(a[1]), "r"(a[2]), "r"(a[3]), "r"(b[0]), "r"(b[1]));
}

// ---------------------------------------------------------------------------
// tf32 tensor-core GEMM (mma.sync): Out[M,Nc] = A[M,K] @ W[K,Nc] + bias (+epi)
// EPI: 0 = bias, 1 = bias + residual, 2 = bias + exact GELU
// Block tile 128x128, BK=32, 256 threads (8 warps, 2x4), warp tile 64x32.
// cp.async double-buffered. SMEM: As[128][36], Bs[32][136] per buffer.
// ---------------------------------------------------------------------------
#define AS_STRIDE 36
#define BS_STRIDE 136
#define A_BYTES (128 * AS_STRIDE * 4)          // 18432
#define B_BYTES (32 * BS_STRIDE * 4)           // 17408
#define BUF_BYTES (A_BYTES + B_BYTES)          // 35840
#define GEMM_SMEM (2 * BUF_BYTES)              // 71680

template <int EPI>
__global__ __launch_bounds__(256)
void gemm_tc(const float* __restrict__ A,
             const float* __restrict__ W,
             const float* __restrict__ bias,
             const float* __restrict__ res,
             float* __restrict__ Out,
             int M, int K, int Nc) {
    extern __shared__ __align__(16) char dyn[];

    const int tid = threadIdx.x;
    const int w = tid >> 5;
    const int lane = tid & 31;
    const int warpRow = w >> 2;      // 0..1
    const int warpCol = w & 3;       // 0..3
    const int rowBase = blockIdx.y * 128;
    const int colBase = blockIdx.x * 128;
    const int nk = K >> 5;

    const uint32_t sbase = smem_u32(dyn);

    // ---- async tile loader: chunk k0 -> buffer buf ----
    auto load_chunk = [&](int buf, int k0) {
        uint32_t aB = sbase + buf * BUF_BYTES;
        uint32_t bB = aB + A_BYTES;
        // A tile: 128 rows x 32 k; 8 segs of 16B per row; 1024 segs / 256 thr = 4
#pragma unroll
        for (int j = 0; j < 4; ++j) {
            int idx = tid + 256 * j;
            int m = idx >> 3, seg = idx & 7;
            int row = rowBase + m; if (row >= M) row = M - 1;
            const float* src = A + (size_t)row * K + k0 + seg * 4;
            CP_ASYNC16(aB + (uint32_t)(m * AS_STRIDE + seg * 4) * 4, src);
        }
        // B tile: 32 k-rows x 128 n; 32 segs of 16B per row
#pragma unroll
        for (int j = 0; j < 4; ++j) {
            int idx = tid + 256 * j;
            int k = idx >> 5, seg = idx & 31;
            const float* src = W + (size_t)(k0 + k) * Nc + colBase + seg * 4;
            CP_ASYNC16(bB + (uint32_t)(k * BS_STRIDE + seg * 4) * 4, src);
        }
    };

    float acc[4][4][4];
#pragma unroll
    for (int i = 0; i < 4; ++i)
#pragma unroll
        for (int j = 0; j < 4; ++j)
#pragma unroll
            for (int r = 0; r < 4; ++r) acc[i][j][r] = 0.f;

    // prologue
    load_chunk(0, 0); CP_COMMIT();
    if (nk > 1) load_chunk(1, 32);
    CP_COMMIT();

    for (int i = 0; i < nk; ++i) {
        if (i + 1 < nk) { CP_WAIT1(); } else { CP_WAIT0(); }
        __syncthreads();

        const uint32_t* sA = (const uint32_t*)(dyn + (i & 1) * BUF_BYTES);
        const uint32_t* sB = (const uint32_t*)(dyn + (i & 1) * BUF_BYTES + A_BYTES);
        const int g = lane >> 2;   // group id 0..7
        const int t4 = lane & 3;   // thread in group 0..3

#pragma unroll
        for (int ks = 0; ks < 4; ++ks) {
            uint32_t af[4][4];
#pragma unroll
            for (int mt = 0; mt < 4; ++mt) {
                const uint32_t* p = sA + (warpRow * 64 + mt * 16 + g) * AS_STRIDE + ks * 8 + t4;
                af[mt][0] = p[0];
                af[mt][1] = p[8 * AS_STRIDE];
                af[mt][2] = p[4];
                af[mt][3] = p[8 * AS_STRIDE + 4];
            }
            uint32_t bf[4][2];
#pragma unroll
            for (int nt = 0; nt < 4; ++nt) {
                const uint32_t* p = sB + (ks * 8 + t4) * BS_STRIDE + warpCol * 32 + nt * 8 + g;
                bf[nt][0] = p[0];
                bf[nt][1] = p[4 * BS_STRIDE];
            }
#pragma unroll
            for (int mt = 0; mt < 4; ++mt)
#pragma unroll
                for (int nt = 0; nt < 4; ++nt)
                    mma_tf32(acc[mt][nt], af[mt], bf[nt]);
        }
        __syncthreads();

        if (i + 2 < nk) { load_chunk(i & 1, (i + 2) * 32); }
        CP_COMMIT();
    }

    // ---- epilogue: registers -> global (float2 stores) ----
    {
        const int g = lane >> 2;
        const int t4 = lane & 3;
#pragma unroll
        for (int mt = 0; mt < 4; ++mt) {
#pragma unroll
            for (int half = 0; half < 2; ++half) {
                int row = rowBase + warpRow * 64 + mt * 16 + half * 8 + g;
                if (row >= M) continue;
#pragma unroll
                for (int nt = 0; nt < 4; ++nt) {
                    int col = colBase + warpCol * 32 + nt * 8 + t4 * 2;
                    float v0 = acc[mt][nt][half * 2 + 0] + bias[col];
                    float v1 = acc[mt][nt][half * 2 + 1] + bias[col + 1];
                    if (EPI == 1) {
                        const float* rp = res + (size_t)row * Nc + col;
                        v0 += rp[0]; v1 += rp[1];
                    }
                    if (EPI == 2) {
                        v0 = 0.5f * v0 * (1.0f + erff(v0 * 0.70710678118654752f));
                        v1 = 0.5f * v1 * (1.0f + erff(v1 * 0.70710678118654752f));
                    }
                    *(float2*)(Out + (size_t)row * Nc + col) = make_float2(v0, v1);
                }
            }
        }
    }
}

// ---------------------------------------------------------------------------
// LayerNorm: one block (256 threads) per row of 768.
// ---------------------------------------------------------------------------
__global__ void ln_kernel(const float* __restrict__ in,
                          const float* __restrict__ gam,
                          const float* __restrict__ bet,
                          float* __restrict__ out,
                          int writeTokens) {
    int row = blockIdx.x;
    const float* xr = in + (size_t)row * CC;
    int tid = threadIdx.x;

    float v[3];
    float s1 = 0.f, s2 = 0.f;
#pragma unroll
    for (int i = 0; i < 3; ++i) {
        v[i] = xr[tid + 256 * i];
        s1 += v[i];
        s2 += v[i] * v[i];
    }
#pragma unroll
    for (int off = 16; off; off >>= 1) {
        s1 += __shfl_xor_sync(0xffffffffu, s1, off);
        s2 += __shfl_xor_sync(0xffffffffu, s2, off);
    }
    __shared__ float sm1[8], sm2[8];
    __shared__ float s_mu, s_rstd;
    int w = tid >> 5;
    if ((tid & 31) == 0) { sm1[w] = s1; sm2[w] = s2; }
    __syncthreads();
    if (tid == 0) {
        float a = 0.f, b2 = 0.f;
#pragma unroll
        for (int i = 0; i < 8; ++i) { a += sm1[i]; b2 += sm2[i]; }
        float mu = a * (1.0f / CC);
        float var = b2 * (1.0f / CC) - mu * mu;
        s_mu = mu;
        s_rstd = rsqrtf(var + LN_EPS);
    }
    __syncthreads();
    float mu = s_mu, rstd = s_rstd;

    float* orow = out + (size_t)row * CC;
    float* trow = nullptr;
    if (writeTokens) {
        int b = row / NN, n = row % NN;
        trow = g_tokens + ((size_t)b * NL + n) * CC;
    }
#pragma unroll
    for (int i = 0; i < 3; ++i) {
        int c = tid + 256 * i;
        float y = (v[i] - mu) * rstd * gam[c] + bet[c];
        orow[c] = y;
        if (writeTokens) trow[c] = y;
    }
}

__global__ void copy_color_kernel(const float* __restrict__ ce) {
    int idx = blockIdx.x * blockDim.x + threadIdx.x;
    const int total = BB * LL * CC;
    if (idx < total) {
        int b = idx / (LL * CC);
        int r = idx % (LL * CC);
        g_tokens[((size_t)b * NL + NN) * CC + r] = ce[idx];
    }
}

// ---------------------------------------------------------------------------
// Flash attention (fp32, online softmax).
// ---------------------------------------------------------------------------
__global__ void attn_kernel(const int* __restrict__ mask) {
    int b = blockIdx.z, h = blockIdx.y, qt = blockIdx.x;

    __shared__ __align__(16) float Qt[64][68];
    __shared__ __align__(16) float Kt[64][34];
    __shared__ __align__(16) float Vs[32][68];
    __shared__ __align__(16) float Ps[64][34];

    int tid = threadIdx.x;
    int tx = tid & 15, ty = tid >> 4;
    int i0 = tid >> 4;
    int d4 = (tid & 15) * 4;

    const float* qbase = g_q + ((size_t)b * NN + qt * 64) * CC + h * DH;
#pragma unroll
    for (int rr = 0; rr < 4; ++rr) {
        int i = i0 + 16 * rr;
        float4 qv = *(const float4*)(qbase + (size_t)i * CC + d4);
        Qt[d4 + 0][i] = qv.x; Qt[d4 + 1][i] = qv.y;
        Qt[d4 + 2][i] = qv.z; Qt[d4 + 3][i] = qv.w;
    }

    float m[4], l[4], o[4][4];
#pragma unroll
    for (int r = 0; r < 4; ++r) {
        m[r] = -1e30f; l[r] = 0.f;
#pragma unroll
        for (int c = 0; c < 4; ++c) o[r][c] = 0.f;
    }

    const int*   mbase  = mask + ((size_t)b * NN + qt * 64) * NL;
    const float* kbase0 = g_k + (size_t)b * NL * CC + h * DH;
    const float* vbase0 = g_v + (size_t)b * NL * CC + h * DH;

    for (int kb = 0; kb < NL; kb += 32) {
        __syncthreads();
#pragma unroll
        for (int rr = 0; rr < 2; ++rr) {
            int j = i0 + 16 * rr;
            int krow = kb + j;
            float4 kv = {0.f, 0.f, 0.f, 0.f};
            float4 vv = {0.f, 0.f, 0.f, 0.f};
            if (krow < NL) {
                kv = *(const float4*)(kbase0 + (size_t)krow * CC + d4);
                vv = *(const float4*)(vbase0 + (size_t)krow * CC + d4);
            }
            Kt[d4 + 0][j] = kv.x; Kt[d4 + 1][j] = kv.y;
            Kt[d4 + 2][j] = kv.z; Kt[d4 + 3][j] = kv.w;
            *(float4*)&Vs[j][d4] = vv;
        }
        __syncthreads();

        float s[4][2] = {};
#pragma unroll 8
        for (int d = 0; d < 64; ++d) {
            float4 q4 = *(const float4*)&Qt[d][ty * 4];
            float2 k2 = *(const float2*)&Kt[d][tx * 2];
            s[0][0] += q4.x * k2.x; s[0][1] += q4.x * k2.y;
            s[1][0] += q4.y * k2.x; s[1][1] += q4.y * k2.y;
            s[2][0] += q4.z * k2.x; s[2][1] += q4.z * k2.y;
            s[3][0] += q4.w * k2.x; s[3][1] += q4.w * k2.y;
        }

#pragma unroll
        for (int r = 0; r < 4; ++r)
#pragma unroll
            for (int c = 0; c < 2; ++c) {
                int col = kb + tx * 2 + c;
                bool ok = (col < NL) &&
                          (mbase[(size_t)(ty * 4 + r) * NL + col] != 0);
                s[r][c] = ok ? s[r][c] * 0.125f : -INFINITY;
            }

#pragma unroll
        for (int r = 0; r < 4; ++r) {
            float cm = fmaxf(s[r][0], s[r][1]);
            cm = fmaxf(cm, __shfl_xor_sync(0xffffffffu, cm, 1));
            cm = fmaxf(cm, __shfl_xor_sync(0xffffffffu, cm, 2));
            cm = fmaxf(cm, __shfl_xor_sync(0xffffffffu, cm, 4));
            cm = fmaxf(cm, __shfl_xor_sync(0xffffffffu, cm, 8));
            float mn = fmaxf(m[r], cm);
            float alpha = __expf(m[r] - mn);
            float p0 = __expf(s[r][0] - mn);
            float p1 = __expf(s[r][1] - mn);
            float rs = p0 + p1;
            rs += __shfl_xor_sync(0xffffffffu, rs, 1);
            rs += __shfl_xor_sync(0xffffffffu, rs, 2);
            rs += __shfl_xor_sync(0xffffffffu, rs, 4);
            rs += __shfl_xor_sync(0xffffffffu, rs, 8);
            l[r] = l[r] * alpha + rs;
            m[r] = mn;
            o[r][0] *= alpha; o[r][1] *= alpha; o[r][2] *= alpha; o[r][3] *= alpha;
            Ps[ty * 4 + r][tx * 2 + 0] = p0;
            Ps[ty * 4 + r][tx * 2 + 1] = p1;
        }
        __syncthreads();

#pragma unroll 4
        for (int j = 0; j < 32; ++j) {
            float4 vv = *(const float4*)&Vs[j][tx * 4];
#pragma unroll
            for (int r = 0; r < 4; ++r) {
                float p = Ps[ty * 4 + r][j];
                o[r][0] += p * vv.x; o[r][1] += p * vv.y;
                o[r][2] += p * vv.z; o[r][3] += p * vv.w;
            }
        }
    }

    float* obase = g_attn + ((size_t)b * NN + qt * 64) * CC + h * DH;
#pragma unroll
    for (int r = 0; r < 4; ++r) {
        float inv = 1.0f / l[r];
        float4 ov = {o[r][0] * inv, o[r][1] * inv, o[r][2] * inv, o[r][3] * inv};
        *(float4*)(obase + (size_t)(ty * 4 + r) * CC + tx * 4) = ov;
    }
}

// ---------------------------------------------------------------------------
// Launch
// ---------------------------------------------------------------------------
extern "C" void kernel_launch(void* const* d_in, const int* in_sizes, int n_in,
                              void* d_out, int out_size) {
    const float* x     = (const float*)d_in[0];
    const float* ce    = (const float*)d_in[1];
    const int*   mask  = (const int*)  d_in[2];
    const float* ln1_g = (const float*)d_in[3];
    const float* ln1_b = (const float*)d_in[4];
    const float* ln2_g = (const float*)d_in[5];
    const float* ln2_b = (const float*)d_in[6];
    const float* Wq = (const float*)d_in[7];
    const float* bq = (const float*)d_in[8];
    const float* Wk = (const float*)d_in[9];
    const float* bk = (const float*)d_in[10];
    const float* Wv = (const float*)d_in[11];
    const float* bv = (const float*)d_in[12];
    const float* Wp = (const float*)d_in[13];
    const float* bp = (const float*)d_in[14];
    const float* W1 = (const float*)d_in[15];
    const float* b1 = (const float*)d_in[16];
    const float* W2 = (const float*)d_in[17];
    const float* b2 = (const float*)d_in[18];
    float* out = (float*)d_out;

    cudaFuncSetAttribute(gemm_tc<0>, cudaFuncAttributeMaxDynamicSharedMemorySize, GEMM_SMEM);
    cudaFuncSetAttribute(gemm_tc<1>, cudaFuncAttributeMaxDynamicSharedMemorySize, GEMM_SMEM);
    cudaFuncSetAttribute(gemm_tc<2>, cudaFuncAttributeMaxDynamicSharedMemorySize, GEMM_SMEM);

    float *p_xn, *p_tokens, *p_q, *p_k, *p_v, *p_attn, *p_x1, *p_h, *p_mlp;
    cudaGetSymbolAddress((void**)&p_xn,     g_xn);
    cudaGetSymbolAddress((void**)&p_tokens, g_tokens);
    cudaGetSymbolAddress((void**)&p_q,      g_q);
    cudaGetSymbolAddress((void**)&p_k,      g_k);
    cudaGetSymbolAddress((void**)&p_v,      g_v);
    cudaGetSymbolAddress((void**)&p_attn,   g_attn);
    cudaGetSymbolAddress((void**)&p_x1,     g_x1);
    cudaGetSymbolAddress((void**)&p_h,      g_h);
    cudaGetSymbolAddress((void**)&p_mlp,    g_mlp);

    const int Mq = BB * NN;     // 16384
    const int Mt = BB * NL;     // 21392
    const int MqT = (Mq + 127) / 128;   // 128
    const int MtT = (Mt + 127) / 128;   // 168

    // 1) LN1 -> xn (+ head of tokens)
    ln_kernel<<<Mq, 256>>>(x, ln1_g, ln1_b, p_xn, 1);
    // 2) tokens tail <- color_emb
    {
        int total = BB * LL * CC;
        copy_color_kernel<<<(total + 255) / 256, 256>>>(ce);
    }
    // 3) Q = xn @ Wq + bq
    gemm_tc<0><<<dim3(CC / 128, MqT), 256, GEMM_SMEM>>>(p_xn, Wq, bq, nullptr, p_q, Mq, CC, CC);
    // 4) K = tokens @ Wk + bk
    gemm_tc<0><<<dim3(CC / 128, MtT), 256, GEMM_SMEM>>>(p_tokens, Wk, bk, nullptr, p_k, Mt, CC, CC);
    // 5) V = tokens @ Wv + bv
    gemm_tc<0><<<dim3(CC / 128, MtT), 256, GEMM_SMEM>>>(p_tokens, Wv, bv, nullptr, p_v, Mt, CC, CC);
    // 6) flash attention -> g_attn
    attn_kernel<<<dim3(NN / 64, HH, BB), 256>>>(mask);
    // 7) x1 = xn + (attn @ Wp + bp)
    gemm_tc<1><<<dim3(CC / 128, MqT), 256, GEMM_SMEM>>>(p_attn, Wp, bp, p_xn, p_x1, Mq, CC, CC);
    // 8) h = LN2(x1)
    ln_kernel<<<Mq, 256>>>(p_x1, ln2_g, ln2_b, p_h, 0);
    // 9) mlp = gelu(h @ W1 + b1)
    gemm_tc<2><<<dim3(MLPD / 128, MqT), 256, GEMM_SMEM>>>(p_h, W1, b1, nullptr, p_mlp, Mq, CC, MLPD);
    // 10) out = x1 + (mlp @ W2 + b2)
    gemm_tc<1><<<dim3(CC / 128, MqT), 256, GEMM_SMEM>>>(p_mlp, W2, b2, p_x1, out, Mq, MLPD, CC);
}

// round 5
// speedup vs baseline: 3.5754x; 2.5354x over previous
#include <cuda_runtime.h>
#include <cuda_bf16.h>
#include <math.h>
#include <stdint.h>

// Problem constants
#define BB 16
#define NN 1024
#define LL 313
#define NL 1337          // N + L
#define CC 768
#define HH 12
#define DH 64
#define MLPD 3072
#define LN_EPS 1e-5f
#define MW 42            // mask words per row = ceil(1337/32)

// ---------------------------------------------------------------------------
// Scratch (device globals; no runtime allocation allowed)
// ---------------------------------------------------------------------------
__device__ float g_xn    [(size_t)BB * NN * CC];
__device__ float g_tokens[(size_t)BB * NL * CC];
__device__ float g_q     [(size_t)BB * NN * CC];
__device__ float g_k     [(size_t)BB * NL * CC];
__device__ float g_v     [(size_t)BB * NL * CC];
__device__ float g_attn  [(size_t)BB * NN * CC];
__device__ float g_x1    [(size_t)BB * NN * CC];
__device__ float g_h     [(size_t)BB * NN * CC];
__device__ float g_mlp   [(size_t)BB * NN * MLPD];
__device__ uint32_t g_mbits[(size_t)BB * NN * MW];

// ---------------------------------------------------------------------------
// Helpers
// ---------------------------------------------------------------------------
__device__ __forceinline__ uint32_t smem_u32(const void* p) {
    uint32_t a;
    asm("{ .reg .u64 t; cvta.to.shared.u64 t, %1; cvt.u32.u64 %0, t; }" : "=r"(a) : "l"(p));
    return a;
}

#define CP_ASYNC16(saddr, gptr) \
    asm volatile("cp.async.cg.shared.global [%0], [%1], 16;" :: "r"(saddr), "l"(gptr))
#define CP_COMMIT() asm volatile("cp.async.commit_group;" ::: "memory")
#define CP_WAIT1()  asm volatile("cp.async.wait_group 1;" ::: "memory")
#define CP_WAIT0()  asm volatile("cp.async.wait_group 0;" ::: "memory")

// mma.sync m16n8k8 tf32: D += A*B  (A row-major 16x8, B col-major 8x8)
__device__ __forceinline__ void mma_tf32(float* d, const uint32_t* a, const uint32_t* b) {
    asm volatile(
        "mma.sync.aligned.m16n8k8.row.col.f32.tf32.tf32.f32 "
        "{%0,%1,%2,%3}, {%4,%5,%6,%7}, {%8,%9}, {%0,%1,%2,%3};"
        : "+f"(d[0]), "+f"(d[1]), "+f"(d[2]), "+f"(d[3])
        : "r"(a[0]), "r"(a[1]), "r"(a[2]), "r"(a[3]), "r"(b[0]), "r"(b[1]));
}

// ---------------------------------------------------------------------------
// tf32 tensor-core GEMM (proven at round 3)
// ---------------------------------------------------------------------------
#define AS_STRIDE 36
#define BS_STRIDE 136
#define A_BYTES (128 * AS_STRIDE * 4)
#define B_BYTES (32 * BS_STRIDE * 4)
#define BUF_BYTES (A_BYTES + B_BYTES)
#define GEMM_SMEM (2 * BUF_BYTES)

template <int EPI>
__global__ __launch_bounds__(256)
void gemm_tc(const float* __restrict__ A,
             const float* __restrict__ W,
             const float* __restrict__ bias,
             const float* __restrict__ res,
             float* __restrict__ Out,
             int M, int K, int Nc) {
    extern __shared__ __align__(16) char dyn[];

    const int tid = threadIdx.x;
    const int w = tid >> 5;
    const int lane = tid & 31;
    const int warpRow = w >> 2;
    const int warpCol = w & 3;
    const int rowBase = blockIdx.y * 128;
    const int colBase = blockIdx.x * 128;
    const int nk = K >> 5;

    const uint32_t sbase = smem_u32(dyn);

    auto load_chunk = [&](int buf, int k0) {
        uint32_t aB = sbase + buf * BUF_BYTES;
        uint32_t bB = aB + A_BYTES;
#pragma unroll
        for (int j = 0; j < 4; ++j) {
            int idx = tid + 256 * j;
            int m = idx >> 3, seg = idx & 7;
            int row = rowBase + m; if (row >= M) row = M - 1;
            const float* src = A + (size_t)row * K + k0 + seg * 4;
            CP_ASYNC16(aB + (uint32_t)(m * AS_STRIDE + seg * 4) * 4, src);
        }
#pragma unroll
        for (int j = 0; j < 4; ++j) {
            int idx = tid + 256 * j;
            int k = idx >> 5, seg = idx & 31;
            const float* src = W + (size_t)(k0 + k) * Nc + colBase + seg * 4;
            CP_ASYNC16(bB + (uint32_t)(k * BS_STRIDE + seg * 4) * 4, src);
        }
    };

    float acc[4][4][4];
#pragma unroll
    for (int i = 0; i < 4; ++i)
#pragma unroll
        for (int j = 0; j < 4; ++j)
#pragma unroll
            for (int r = 0; r < 4; ++r) acc[i][j][r] = 0.f;

    load_chunk(0, 0); CP_COMMIT();
    if (nk > 1) load_chunk(1, 32);
    CP_COMMIT();

    for (int i = 0; i < nk; ++i) {
        if (i + 1 < nk) { CP_WAIT1(); } else { CP_WAIT0(); }
        __syncthreads();

        const uint32_t* sA = (const uint32_t*)(dyn + (i & 1) * BUF_BYTES);
        const uint32_t* sB = (const uint32_t*)(dyn + (i & 1) * BUF_BYTES + A_BYTES);
        const int g = lane >> 2;
        const int t4 = lane & 3;

#pragma unroll
        for (int ks = 0; ks < 4; ++ks) {
            uint32_t af[4][4];
#pragma unroll
            for (int mt = 0; mt < 4; ++mt) {
                const uint32_t* p = sA + (warpRow * 64 + mt * 16 + g) * AS_STRIDE + ks * 8 + t4;
                af[mt][0] = p[0];
                af[mt][1] = p[8 * AS_STRIDE];
                af[mt][2] = p[4];
                af[mt][3] = p[8 * AS_STRIDE + 4];
            }
            uint32_t bf[4][2];
#pragma unroll
            for (int nt = 0; nt < 4; ++nt) {
                const uint32_t* p = sB + (ks * 8 + t4) * BS_STRIDE + warpCol * 32 + nt * 8 + g;
                bf[nt][0] = p[0];
                bf[nt][1] = p[4 * BS_STRIDE];
            }
#pragma unroll
            for (int mt = 0; mt < 4; ++mt)
#pragma unroll
                for (int nt = 0; nt < 4; ++nt)
                    mma_tf32(acc[mt][nt], af[mt], bf[nt]);
        }
        __syncthreads();

        if (i + 2 < nk) { load_chunk(i & 1, (i + 2) * 32); }
        CP_COMMIT();
    }

    {
        const int g = lane >> 2;
        const int t4 = lane & 3;
#pragma unroll
        for (int mt = 0; mt < 4; ++mt) {
#pragma unroll
            for (int half = 0; half < 2; ++half) {
                int row = rowBase + warpRow * 64 + mt * 16 + half * 8 + g;
                if (row >= M) continue;
#pragma unroll
                for (int nt = 0; nt < 4; ++nt) {
                    int col = colBase + warpCol * 32 + nt * 8 + t4 * 2;
                    float v0 = acc[mt][nt][half * 2 + 0] + bias[col];
                    float v1 = acc[mt][nt][half * 2 + 1] + bias[col + 1];
                    if (EPI == 1) {
                        const float* rp = res + (size_t)row * Nc + col;
                        v0 += rp[0]; v1 += rp[1];
                    }
                    if (EPI == 2) {
                        v0 = 0.5f * v0 * (1.0f + erff(v0 * 0.70710678118654752f));
                        v1 = 0.5f * v1 * (1.0f + erff(v1 * 0.70710678118654752f));
                    }
                    *(float2*)(Out + (size_t)row * Nc + col) = make_float2(v0, v1);
                }
            }
        }
    }
}

// ---------------------------------------------------------------------------
// LayerNorm
// ---------------------------------------------------------------------------
__global__ void ln_kernel(const float* __restrict__ in,
                          const float* __restrict__ gam,
                          const float* __restrict__ bet,
                          float* __restrict__ out,
                          int writeTokens) {
    int row = blockIdx.x;
    const float* xr = in + (size_t)row * CC;
    int tid = threadIdx.x;

    float v[3];
    float s1 = 0.f, s2 = 0.f;
#pragma unroll
    for (int i = 0; i < 3; ++i) {
        v[i] = xr[tid + 256 * i];
        s1 += v[i];
        s2 += v[i] * v[i];
    }
#pragma unroll
    for (int off = 16; off; off >>= 1) {
        s1 += __shfl_xor_sync(0xffffffffu, s1, off);
        s2 += __shfl_xor_sync(0xffffffffu, s2, off);
    }
    __shared__ float sm1[8], sm2[8];
    __shared__ float s_mu, s_rstd;
    int w = tid >> 5;
    if ((tid & 31) == 0) { sm1[w] = s1; sm2[w] = s2; }
    __syncthreads();
    if (tid == 0) {
        float a = 0.f, b2 = 0.f;
#pragma unroll
        for (int i = 0; i < 8; ++i) { a += sm1[i]; b2 += sm2[i]; }
        float mu = a * (1.0f / CC);
        float var = b2 * (1.0f / CC) - mu * mu;
        s_mu = mu;
        s_rstd = rsqrtf(var + LN_EPS);
    }
    __syncthreads();
    float mu = s_mu, rstd = s_rstd;

    float* orow = out + (size_t)row * CC;
    float* trow = nullptr;
    if (writeTokens) {
        int b = row / NN, n = row % NN;
        trow = g_tokens + ((size_t)b * NL + n) * CC;
    }
#pragma unroll
    for (int i = 0; i < 3; ++i) {
        int c = tid + 256 * i;
        float y = (v[i] - mu) * rstd * gam[c] + bet[c];
        orow[c] = y;
        if (writeTokens) trow[c] = y;
    }
}

__global__ void copy_color_kernel(const float* __restrict__ ce) {
    int idx = blockIdx.x * blockDim.x + threadIdx.x;
    const int total = BB * LL * CC;
    if (idx < total) {
        int b = idx / (LL * CC);
        int r = idx % (LL * CC);
        g_tokens[((size_t)b * NL + NN) * CC + r] = ce[idx];
    }
}

// ---------------------------------------------------------------------------
// Mask bit-pack: mask[B*N][NL] int32 -> g_mbits[B*N][42]
// ---------------------------------------------------------------------------
__global__ void pack_mask_kernel(const int* __restrict__ mask) {
    int idx = blockIdx.x * blockDim.x + threadIdx.x;
    const int total = BB * NN * MW;
    if (idx >= total) return;
    int row = idx / MW, wd = idx % MW;
    const int* mp = mask + (size_t)row * NL + wd * 32;
    int nb = NL - wd * 32; if (nb > 32) nb = 32;
    uint32_t bits = 0;
    for (int t = 0; t < nb; ++t)
        if (mp[t] != 0) bits |= (1u << t);
    g_mbits[idx] = bits;
}

// ---------------------------------------------------------------------------
// Tensor-core flash attention (tf32 mma.sync).
// Grid (N/128, H, B), 256 threads (8 warps). Warp owns 16 query rows.
// K/V chunks of 64 keys, double-buffered cp.async.
// SMEM layout (floats): Ks[2][64*68], Vs[2][64*68], Ps[8][16*68]
// ---------------------------------------------------------------------------
#define KV_STRIDE 68
#define KV_TILE (64 * KV_STRIDE)                 // 4352 floats
#define ATT_SMEM ((4 * KV_TILE + 8 * 16 * KV_STRIDE) * 4)  // 104448 bytes
#define ATT_NC 21                                // ceil(1337/64)

__global__ __launch_bounds__(256)
void attn_tc(const uint32_t* __restrict__ mbits) {
    extern __shared__ __align__(16) float sm[];
    const int b = blockIdx.z, h = blockIdx.y, qt = blockIdx.x;
    const int tid = threadIdx.x;
    const int w = tid >> 5, lane = tid & 31;
    const int g = lane >> 2, t4 = lane & 3;

    float* Ksm = sm;                      // [2][KV_TILE]
    float* Vsm = sm + 2 * KV_TILE;        // [2][KV_TILE]
    float* Ps  = sm + 4 * KV_TILE + w * (16 * KV_STRIDE);
    const uint32_t ks_addr = smem_u32(Ksm);
    const uint32_t vs_addr = smem_u32(Vsm);

    // ---- Q fragments (registers, scaled by 1/sqrt(DH)) ----
    uint32_t aq[8][4];
    {
        const float* qp = g_q + ((size_t)(b * NN + qt * 128 + w * 16)) * CC + h * DH;
#pragma unroll
        for (int ks = 0; ks < 8; ++ks) {
            aq[ks][0] = __float_as_uint(qp[(size_t)g * CC + ks * 8 + t4] * 0.125f);
            aq[ks][1] = __float_as_uint(qp[(size_t)(g + 8) * CC + ks * 8 + t4] * 0.125f);
            aq[ks][2] = __float_as_uint(qp[(size_t)g * CC + ks * 8 + t4 + 4] * 0.125f);
            aq[ks][3] = __float_as_uint(qp[(size_t)(g + 8) * CC + ks * 8 + t4 + 4] * 0.125f);
        }
    }

    const uint32_t* mrow0 = mbits + (size_t)(b * NN + qt * 128 + w * 16 + g) * MW;
    const uint32_t* mrow1 = mrow0 + (size_t)8 * MW;

    // ---- K/V chunk loader (FIXED: all 16 segments of DH=64 per token) ----
    auto load_kv = [&](int buf, int kb) {
        int j = tid >> 2;          // token 0..63
        int s0 = tid & 3;          // base segment
        int tok = kb + j; if (tok >= NL) tok = NL - 1;
        const float* ksrc = g_k + ((size_t)b * NL + tok) * CC + h * DH;
        const float* vsrc = g_v + ((size_t)b * NL + tok) * CC + h * DH;
        uint32_t off = (uint32_t)(buf * KV_TILE + j * KV_STRIDE) * 4;
#pragma unroll
        for (int it = 0; it < 4; ++it) {
            int seg = s0 + it * 4;           // 0..15
            CP_ASYNC16(ks_addr + off + seg * 16, ksrc + seg * 4);
            CP_ASYNC16(vs_addr + off + seg * 16, vsrc + seg * 4);
        }
    };

    float m0 = -1e30f, m1 = -1e30f, l0 = 0.f, l1 = 0.f;
    float o[8][4];
#pragma unroll
    for (int nt = 0; nt < 8; ++nt)
#pragma unroll
        for (int r = 0; r < 4; ++r) o[nt][r] = 0.f;

    load_kv(0, 0); CP_COMMIT();

    for (int c = 0; c < ATT_NC; ++c) {
        const int kb = c * 64;
        if (c + 1 < ATT_NC) load_kv((c + 1) & 1, kb + 64);
        CP_COMMIT();
        if (c + 1 < ATT_NC) { CP_WAIT1(); } else { CP_WAIT0(); }
        __syncthreads();

        const float* K = Ksm + (c & 1) * KV_TILE;
        const float* V = Vsm + (c & 1) * KV_TILE;

        const int wb = kb >> 5;
        const uint32_t mw00 = mrow0[wb], mw01 = mrow0[wb + 1];
        const uint32_t mw10 = mrow1[wb], mw11 = mrow1[wb + 1];

        // ---- S = Q K^T ----
        float s[8][4];
#pragma unroll
        for (int nt = 0; nt < 8; ++nt) {
            s[nt][0] = s[nt][1] = s[nt][2] = s[nt][3] = 0.f;
            const float* kp = K + (nt * 8 + g) * KV_STRIDE;
#pragma unroll
            for (int ks = 0; ks < 8; ++ks) {
                uint32_t bf[2];
                bf[0] = __float_as_uint(kp[ks * 8 + t4]);
                bf[1] = __float_as_uint(kp[ks * 8 + t4 + 4]);
                mma_tf32(s[nt], aq[ks], bf);
            }
        }

        // ---- mask + online softmax ----
        float cm0 = -INFINITY, cm1 = -INFINITY;
#pragma unroll
        for (int nt = 0; nt < 8; ++nt) {
            int colb = nt * 8 + t4 * 2;
            uint32_t wr0 = (colb < 32) ? mw00 : mw01;
            uint32_t wr1 = (colb < 32) ? mw10 : mw11;
            int sh = colb & 31;
            s[nt][0] = ((wr0 >> sh) & 1u)       ? s[nt][0] : -INFINITY;
            s[nt][1] = ((wr0 >> (sh + 1)) & 1u) ? s[nt][1] : -INFINITY;
            s[nt][2] = ((wr1 >> sh) & 1u)       ? s[nt][2] : -INFINITY;
            s[nt][3] = ((wr1 >> (sh + 1)) & 1u) ? s[nt][3] : -INFINITY;
            cm0 = fmaxf(cm0, fmaxf(s[nt][0], s[nt][1]));
            cm1 = fmaxf(cm1, fmaxf(s[nt][2], s[nt][3]));
        }
        cm0 = fmaxf(cm0, __shfl_xor_sync(0xffffffffu, cm0, 1));
        cm0 = fmaxf(cm0, __shfl_xor_sync(0xffffffffu, cm0, 2));
        cm1 = fmaxf(cm1, __shfl_xor_sync(0xffffffffu, cm1, 1));
        cm1 = fmaxf(cm1, __shfl_xor_sync(0xffffffffu, cm1, 2));

        float mn0 = fmaxf(m0, cm0), mn1 = fmaxf(m1, cm1);
        float al0 = __expf(m0 - mn0), al1 = __expf(m1 - mn1);

        float rs0 = 0.f, rs1 = 0.f;
#pragma unroll
        for (int nt = 0; nt < 8; ++nt) {
            int colb = nt * 8 + t4 * 2;
            float p0 = __expf(s[nt][0] - mn0);
            float p1 = __expf(s[nt][1] - mn0);
            float p2 = __expf(s[nt][2] - mn1);
            float p3 = __expf(s[nt][3] - mn1);
            rs0 += p0 + p1; rs1 += p2 + p3;
            *(float2*)&Ps[g * KV_STRIDE + colb]       = make_float2(p0, p1);
            *(float2*)&Ps[(8 + g) * KV_STRIDE + colb] = make_float2(p2, p3);
        }
        rs0 += __shfl_xor_sync(0xffffffffu, rs0, 1);
        rs0 += __shfl_xor_sync(0xffffffffu, rs0, 2);
        rs1 += __shfl_xor_sync(0xffffffffu, rs1, 1);
        rs1 += __shfl_xor_sync(0xffffffffu, rs1, 2);

        l0 = l0 * al0 + rs0;  m0 = mn0;
        l1 = l1 * al1 + rs1;  m1 = mn1;
#pragma unroll
        for (int nt = 0; nt < 8; ++nt) {
            o[nt][0] *= al0; o[nt][1] *= al0;
            o[nt][2] *= al1; o[nt][3] *= al1;
        }
        __syncwarp();

        // ---- O += P V ----
#pragma unroll
        for (int ks = 0; ks < 8; ++ks) {
            uint32_t ap[4];
            ap[0] = __float_as_uint(Ps[g * KV_STRIDE + ks * 8 + t4]);
            ap[1] = __float_as_uint(Ps[(8 + g) * KV_STRIDE + ks * 8 + t4]);
            ap[2] = __float_as_uint(Ps[g * KV_STRIDE + ks * 8 + t4 + 4]);
            ap[3] = __float_as_uint(Ps[(8 + g) * KV_STRIDE + ks * 8 + t4 + 4]);
            const float* vp0 = V + (ks * 8 + t4) * KV_STRIDE;
            const float* vp1 = V + (ks * 8 + t4 + 4) * KV_STRIDE;
#pragma unroll
            for (int nt = 0; nt < 8; ++nt) {
                uint32_t bf[2];
                bf[0] = __float_as_uint(vp0[nt * 8 + g]);
                bf[1] = __float_as_uint(vp1[nt * 8 + g]);
                mma_tf32(o[nt], ap, bf);
            }
        }
        __syncthreads();
    }

    // ---- normalize + store ----
    {
        float inv0 = 1.0f / l0, inv1 = 1.0f / l1;
        float* ob = g_attn + ((size_t)(b * NN + qt * 128 + w * 16)) * CC + h * DH;
#pragma unroll
        for (int nt = 0; nt < 8; ++nt) {
            int col = nt * 8 + t4 * 2;
            *(float2*)(ob + (size_t)g * CC + col) =
                make_float2(o[nt][0] * inv0, o[nt][1] * inv0);
            *(float2*)(ob + (size_t)(8 + g) * CC + col) =
                make_float2(o[nt][2] * inv1, o[nt][3] * inv1);
        }
    }
}

// ---------------------------------------------------------------------------
// Launch
// ---------------------------------------------------------------------------
extern "C" void kernel_launch(void* const* d_in, const int* in_sizes, int n_in,
                              void* d_out, int out_size) {
    const float* x     = (const float*)d_in[0];
    const float* ce    = (const float*)d_in[1];
    const int*   mask  = (const int*)  d_in[2];
    const float* ln1_g = (const float*)d_in[3];
    const float* ln1_b = (const float*)d_in[4];
    const float* ln2_g = (const float*)d_in[5];
    const float* ln2_b = (const float*)d_in[6];
    const float* Wq = (const float*)d_in[7];
    const float* bq = (const float*)d_in[8];
    const float* Wk = (const float*)d_in[9];
    const float* bk = (const float*)d_in[10];
    const float* Wv = (const float*)d_in[11];
    const float* bv = (const float*)d_in[12];
    const float* Wp = (const float*)d_in[13];
    const float* bp = (const float*)d_in[14];
    const float* W1 = (const float*)d_in[15];
    const float* b1 = (const float*)d_in[16];
    const float* W2 = (const float*)d_in[17];
    const float* b2 = (const float*)d_in[18];
    float* out = (float*)d_out;

    cudaFuncSetAttribute(gemm_tc<0>, cudaFuncAttributeMaxDynamicSharedMemorySize, GEMM_SMEM);
    cudaFuncSetAttribute(gemm_tc<1>, cudaFuncAttributeMaxDynamicSharedMemorySize, GEMM_SMEM);
    cudaFuncSetAttribute(gemm_tc<2>, cudaFuncAttributeMaxDynamicSharedMemorySize, GEMM_SMEM);
    cudaFuncSetAttribute(attn_tc,    cudaFuncAttributeMaxDynamicSharedMemorySize, ATT_SMEM);

    float *p_xn, *p_tokens, *p_q, *p_k, *p_v, *p_attn, *p_x1, *p_h, *p_mlp;
    uint32_t* p_mbits;
    cudaGetSymbolAddress((void**)&p_xn,     g_xn);
    cudaGetSymbolAddress((void**)&p_tokens, g_tokens);
    cudaGetSymbolAddress((void**)&p_q,      g_q);
    cudaGetSymbolAddress((void**)&p_k,      g_k);
    cudaGetSymbolAddress((void**)&p_v,      g_v);
    cudaGetSymbolAddress((void**)&p_attn,   g_attn);
    cudaGetSymbolAddress((void**)&p_x1,     g_x1);
    cudaGetSymbolAddress((void**)&p_h,      g_h);
    cudaGetSymbolAddress((void**)&p_mlp,    g_mlp);
    cudaGetSymbolAddress((void**)&p_mbits,  g_mbits);

    const int Mq = BB * NN;     // 16384
    const int Mt = BB * NL;     // 21392
    const int MqT = (Mq + 127) / 128;
    const int MtT = (Mt + 127) / 128;

    // 1) LN1 -> xn (+ head of tokens); pack mask bits
    ln_kernel<<<Mq, 256>>>(x, ln1_g, ln1_b, p_xn, 1);
    {
        int totalw = BB * NN * MW;
        pack_mask_kernel<<<(totalw + 255) / 256, 256>>>(mask);
    }
    // 2) tokens tail <- color_emb
    {
        int total = BB * LL * CC;
        copy_color_kernel<<<(total + 255) / 256, 256>>>(ce);
    }
    // 3) Q = xn @ Wq + bq
    gemm_tc<0><<<dim3(CC / 128, MqT), 256, GEMM_SMEM>>>(p_xn, Wq, bq, nullptr, p_q, Mq, CC, CC);
    // 4) K = tokens @ Wk + bk
    gemm_tc<0><<<dim3(CC / 128, MtT), 256, GEMM_SMEM>>>(p_tokens, Wk, bk, nullptr, p_k, Mt, CC, CC);
    // 5) V = tokens @ Wv + bv
    gemm_tc<0><<<dim3(CC / 128, MtT), 256, GEMM_SMEM>>>(p_tokens, Wv, bv, nullptr, p_v, Mt, CC, CC);
    // 6) tensor-core flash attention -> g_attn
    attn_tc<<<dim3(NN / 128, HH, BB), 256, ATT_SMEM>>>(p_mbits);
    // 7) x1 = xn + (attn @ Wp + bp)
    gemm_tc<1><<<dim3(CC / 128, MqT), 256, GEMM_SMEM>>>(p_attn, Wp, bp, p_xn, p_x1, Mq, CC, CC);
    // 8) h = LN2(x1)
    ln_kernel<<<Mq, 256>>>(p_x1, ln2_g, ln2_b, p_h, 0);
    // 9) mlp = gelu(h @ W1 + b1)
    gemm_tc<2><<<dim3(MLPD / 128, MqT), 256, GEMM_SMEM>>>(p_h, W1, b1, nullptr, p_mlp, Mq, CC, MLPD);
    // 10) out = x1 + (mlp @ W2 + b2)
    gemm_tc<1><<<dim3(CC / 128, MqT), 256, GEMM_SMEM>>>(p_mlp, W2, b2, p_x1, out, Mq, MLPD, CC);
}

// round 6
// speedup vs baseline: 3.7592x; 1.0514x over previous
#include <cuda_runtime.h>
#include <cuda_bf16.h>
#include <math.h>
#include <stdint.h>

// Problem constants
#define BB 16
#define NN 1024
#define LL 313
#define NL 1337          // N + L
#define CC 768
#define HH 12
#define DH 64
#define MLPD 3072
#define LN_EPS 1e-5f
#define MW 42            // mask words per row = ceil(1337/32)

// ---------------------------------------------------------------------------
// Scratch (device globals; no runtime allocation allowed)
// ---------------------------------------------------------------------------
__device__ float g_xn    [(size_t)BB * NN * CC];
__device__ float g_tokens[(size_t)BB * NL * CC];
__device__ float g_q     [(size_t)BB * NN * CC];
__device__ float g_k     [(size_t)BB * NL * CC];
__device__ float g_v     [(size_t)BB * NL * CC];
__device__ float g_attn  [(size_t)BB * NN * CC];
__device__ float g_x1    [(size_t)BB * NN * CC];
__device__ float g_h     [(size_t)BB * NN * CC];
__device__ float g_mlp   [(size_t)BB * NN * MLPD];
__device__ uint32_t g_mbits[(size_t)BB * NN * MW];

// ---------------------------------------------------------------------------
// Helpers
// ---------------------------------------------------------------------------
__device__ __forceinline__ uint32_t smem_u32(const void* p) {
    uint32_t a;
    asm("{ .reg .u64 t; cvta.to.shared.u64 t, %1; cvt.u32.u64 %0, t; }" : "=r"(a) : "l"(p));
    return a;
}

#define CP_ASYNC16(saddr, gptr) \
    asm volatile("cp.async.cg.shared.global [%0], [%1], 16;" :: "r"(saddr), "l"(gptr))
#define CP_COMMIT() asm volatile("cp.async.commit_group;" ::: "memory")
#define CP_WAIT1()  asm volatile("cp.async.wait_group 1;" ::: "memory")
#define CP_WAIT0()  asm volatile("cp.async.wait_group 0;" ::: "memory")

// mma.sync m16n8k8 tf32: D += A*B  (A row-major 16x8, B col-major 8x8)
__device__ __forceinline__ void mma_tf32(float* d, const uint32_t* a, const uint32_t* b) {
    asm volatile(
        "mma.sync.aligned.m16n8k8.row.col.f32.tf32.tf32.f32 "
        "{%0,%1,%2,%3}, {%4,%5,%6,%7}, {%8,%9}, {%0,%1,%2,%3};"
        : "+f"(d[0]), "+f"(d[1]), "+f"(d[2]), "+f"(d[3])
        : "r"(a[0]), "r"(a[1]), "r"(a[2]), "r"(a[3]), "r"(b[0]), "r"(b[1]));
}

// ---------------------------------------------------------------------------
// tf32 tensor-core GEMM — 3-stage cp.async pipeline, one barrier per iter.
// Out[M,Nc] = A[M,K] @ W[K,Nc] + bias (+epi)
// Block tile 128x128, BK=32, 256 threads (8 warps, 2x4), warp tile 64x32.
// ---------------------------------------------------------------------------
#define AS_STRIDE 36
#define BS_STRIDE 136
#define A_BYTES (128 * AS_STRIDE * 4)
#define B_BYTES (32 * BS_STRIDE * 4)
#define BUF_BYTES (A_BYTES + B_BYTES)          // 35840
#define NSTAGE 3
#define GEMM_SMEM (NSTAGE * BUF_BYTES)         // 107520

template <int EPI>
__global__ __launch_bounds__(256)
void gemm_tc(const float* __restrict__ A,
             const float* __restrict__ W,
             const float* __restrict__ bias,
             const float* __restrict__ res,
             float* __restrict__ Out,
             int M, int K, int Nc) {
    extern __shared__ __align__(16) char dyn[];

    const int tid = threadIdx.x;
    const int w = tid >> 5;
    const int lane = tid & 31;
    const int warpRow = w >> 2;
    const int warpCol = w & 3;
    const int rowBase = blockIdx.y * 128;
    const int colBase = blockIdx.x * 128;
    const int nk = K >> 5;

    const uint32_t sbase = smem_u32(dyn);

    auto load_chunk = [&](int buf, int k0) {
        uint32_t aB = sbase + buf * BUF_BYTES;
        uint32_t bB = aB + A_BYTES;
#pragma unroll
        for (int j = 0; j < 4; ++j) {
            int idx = tid + 256 * j;
            int m = idx >> 3, seg = idx & 7;
            int row = rowBase + m; if (row >= M) row = M - 1;
            const float* src = A + (size_t)row * K + k0 + seg * 4;
            CP_ASYNC16(aB + (uint32_t)(m * AS_STRIDE + seg * 4) * 4, src);
        }
#pragma unroll
        for (int j = 0; j < 4; ++j) {
            int idx = tid + 256 * j;
            int k = idx >> 5, seg = idx & 31;
            const float* src = W + (size_t)(k0 + k) * Nc + colBase + seg * 4;
            CP_ASYNC16(bB + (uint32_t)(k * BS_STRIDE + seg * 4) * 4, src);
        }
    };

    float acc[4][4][4];
#pragma unroll
    for (int i = 0; i < 4; ++i)
#pragma unroll
        for (int j = 0; j < 4; ++j)
#pragma unroll
            for (int r = 0; r < 4; ++r) acc[i][j][r] = 0.f;

    // prologue: stages 0 and 1 in flight
    load_chunk(0, 0); CP_COMMIT();
    load_chunk(1, 32); CP_COMMIT();          // nk >= 24 for all calls here

    int buf = 0;
    for (int i = 0; i < nk; ++i) {
        CP_WAIT1();              // stage i resident (always 2 groups pending)
        __syncthreads();         // single barrier per iteration

        const uint32_t* sA = (const uint32_t*)(dyn + buf * BUF_BYTES);
        const uint32_t* sB = (const uint32_t*)(dyn + buf * BUF_BYTES + A_BYTES);
        const int g = lane >> 2;
        const int t4 = lane & 3;

#pragma unroll
        for (int ks = 0; ks < 4; ++ks) {
            uint32_t af[4][4];
#pragma unroll
            for (int mt = 0; mt < 4; ++mt) {
                const uint32_t* p = sA + (warpRow * 64 + mt * 16 + g) * AS_STRIDE + ks * 8 + t4;
                af[mt][0] = p[0];
                af[mt][1] = p[8 * AS_STRIDE];
                af[mt][2] = p[4];
                af[mt][3] = p[8 * AS_STRIDE + 4];
            }
            uint32_t bf[4][2];
#pragma unroll
            for (int nt = 0; nt < 4; ++nt) {
                const uint32_t* p = sB + (ks * 8 + t4) * BS_STRIDE + warpCol * 32 + nt * 8 + g;
                bf[nt][0] = p[0];
                bf[nt][1] = p[4 * BS_STRIDE];
            }
#pragma unroll
            for (int mt = 0; mt < 4; ++mt)
#pragma unroll
                for (int nt = 0; nt < 4; ++nt)
                    mma_tf32(acc[mt][nt], af[mt], bf[nt]);
        }

        // issue loads for stage i+2 into the stage freed at iter i-1's barrier
        if (i + 2 < nk) load_chunk((buf + 2) % NSTAGE, (i + 2) * 32);
        CP_COMMIT();             // unconditional: keeps pending-group count = 2
        buf = (buf + 1) % NSTAGE;
    }

    {
        const int g = lane >> 2;
        const int t4 = lane & 3;
#pragma unroll
        for (int mt = 0; mt < 4; ++mt) {
#pragma unroll
            for (int half = 0; half < 2; ++half) {
                int row = rowBase + warpRow * 64 + mt * 16 + half * 8 + g;
                if (row >= M) continue;
#pragma unroll
                for (int nt = 0; nt < 4; ++nt) {
                    int col = colBase + warpCol * 32 + nt * 8 + t4 * 2;
                    float v0 = acc[mt][nt][half * 2 + 0] + bias[col];
                    float v1 = acc[mt][nt][half * 2 + 1] + bias[col + 1];
                    if (EPI == 1) {
                        const float* rp = res + (size_t)row * Nc + col;
                        v0 += rp[0]; v1 += rp[1];
                    }
                    if (EPI == 2) {
                        v0 = 0.5f * v0 * (1.0f + erff(v0 * 0.70710678118654752f));
                        v1 = 0.5f * v1 * (1.0f + erff(v1 * 0.70710678118654752f));
                    }
                    *(float2*)(Out + (size_t)row * Nc + col) = make_float2(v0, v1);
                }
            }
        }
    }
}

// ---------------------------------------------------------------------------
// LayerNorm
// ---------------------------------------------------------------------------
__global__ void ln_kernel(const float* __restrict__ in,
                          const float* __restrict__ gam,
                          const float* __restrict__ bet,
                          float* __restrict__ out,
                          int writeTokens) {
    int row = blockIdx.x;
    const float* xr = in + (size_t)row * CC;
    int tid = threadIdx.x;

    float v[3];
    float s1 = 0.f, s2 = 0.f;
#pragma unroll
    for (int i = 0; i < 3; ++i) {
        v[i] = xr[tid + 256 * i];
        s1 += v[i];
        s2 += v[i] * v[i];
    }
#pragma unroll
    for (int off = 16; off; off >>= 1) {
        s1 += __shfl_xor_sync(0xffffffffu, s1, off);
        s2 += __shfl_xor_sync(0xffffffffu, s2, off);
    }
    __shared__ float sm1[8], sm2[8];
    __shared__ float s_mu, s_rstd;
    int w = tid >> 5;
    if ((tid & 31) == 0) { sm1[w] = s1; sm2[w] = s2; }
    __syncthreads();
    if (tid == 0) {
        float a = 0.f, b2 = 0.f;
#pragma unroll
        for (int i = 0; i < 8; ++i) { a += sm1[i]; b2 += sm2[i]; }
        float mu = a * (1.0f / CC);
        float var = b2 * (1.0f / CC) - mu * mu;
        s_mu = mu;
        s_rstd = rsqrtf(var + LN_EPS);
    }
    __syncthreads();
    float mu = s_mu, rstd = s_rstd;

    float* orow = out + (size_t)row * CC;
    float* trow = nullptr;
    if (writeTokens) {
        int b = row / NN, n = row % NN;
        trow = g_tokens + ((size_t)b * NL + n) * CC;
    }
#pragma unroll
    for (int i = 0; i < 3; ++i) {
        int c = tid + 256 * i;
        float y = (v[i] - mu) * rstd * gam[c] + bet[c];
        orow[c] = y;
        if (writeTokens) trow[c] = y;
    }
}

__global__ void copy_color_kernel(const float* __restrict__ ce) {
    int idx = blockIdx.x * blockDim.x + threadIdx.x;
    const int total = BB * LL * CC;
    if (idx < total) {
        int b = idx / (LL * CC);
        int r = idx % (LL * CC);
        g_tokens[((size_t)b * NL + NN) * CC + r] = ce[idx];
    }
}

// ---------------------------------------------------------------------------
// Mask bit-pack: mask[B*N][NL] int32 -> g_mbits[B*N][42]
// ---------------------------------------------------------------------------
__global__ void pack_mask_kernel(const int* __restrict__ mask) {
    int idx = blockIdx.x * blockDim.x + threadIdx.x;
    const int total = BB * NN * MW;
    if (idx >= total) return;
    int row = idx / MW, wd = idx % MW;
    const int* mp = mask + (size_t)row * NL + wd * 32;
    int nb = NL - wd * 32; if (nb > 32) nb = 32;
    uint32_t bits = 0;
    for (int t = 0; t < nb; ++t)
        if (mp[t] != 0) bits |= (1u << t);
    g_mbits[idx] = bits;
}

// ---------------------------------------------------------------------------
// Tensor-core flash attention (tf32 mma.sync) — proven at round 5.
// ---------------------------------------------------------------------------
#define KV_STRIDE 68
#define KV_TILE (64 * KV_STRIDE)
#define ATT_SMEM ((4 * KV_TILE + 8 * 16 * KV_STRIDE) * 4)  // 104448 bytes
#define ATT_NC 21

__global__ __launch_bounds__(256)
void attn_tc(const uint32_t* __restrict__ mbits) {
    extern __shared__ __align__(16) float sm[];
    const int b = blockIdx.z, h = blockIdx.y, qt = blockIdx.x;
    const int tid = threadIdx.x;
    const int w = tid >> 5, lane = tid & 31;
    const int g = lane >> 2, t4 = lane & 3;

    float* Ksm = sm;
    float* Vsm = sm + 2 * KV_TILE;
    float* Ps  = sm + 4 * KV_TILE + w * (16 * KV_STRIDE);
    const uint32_t ks_addr = smem_u32(Ksm);
    const uint32_t vs_addr = smem_u32(Vsm);

    uint32_t aq[8][4];
    {
        const float* qp = g_q + ((size_t)(b * NN + qt * 128 + w * 16)) * CC + h * DH;
#pragma unroll
        for (int ks = 0; ks < 8; ++ks) {
            aq[ks][0] = __float_as_uint(qp[(size_t)g * CC + ks * 8 + t4] * 0.125f);
            aq[ks][1] = __float_as_uint(qp[(size_t)(g + 8) * CC + ks * 8 + t4] * 0.125f);
            aq[ks][2] = __float_as_uint(qp[(size_t)g * CC + ks * 8 + t4 + 4] * 0.125f);
            aq[ks][3] = __float_as_uint(qp[(size_t)(g + 8) * CC + ks * 8 + t4 + 4] * 0.125f);
        }
    }

    const uint32_t* mrow0 = mbits + (size_t)(b * NN + qt * 128 + w * 16 + g) * MW;
    const uint32_t* mrow1 = mrow0 + (size_t)8 * MW;

    auto load_kv = [&](int buf, int kb) {
        int j = tid >> 2;
        int s0 = tid & 3;
        int tok = kb + j; if (tok >= NL) tok = NL - 1;
        const float* ksrc = g_k + ((size_t)b * NL + tok) * CC + h * DH;
        const float* vsrc = g_v + ((size_t)b * NL + tok) * CC + h * DH;
        uint32_t off = (uint32_t)(buf * KV_TILE + j * KV_STRIDE) * 4;
#pragma unroll
        for (int it = 0; it < 4; ++it) {
            int seg = s0 + it * 4;
            CP_ASYNC16(ks_addr + off + seg * 16, ksrc + seg * 4);
            CP_ASYNC16(vs_addr + off + seg * 16, vsrc + seg * 4);
        }
    };

    float m0 = -1e30f, m1 = -1e30f, l0 = 0.f, l1 = 0.f;
    float o[8][4];
#pragma unroll
    for (int nt = 0; nt < 8; ++nt)
#pragma unroll
        for (int r = 0; r < 4; ++r) o[nt][r] = 0.f;

    load_kv(0, 0); CP_COMMIT();

    for (int c = 0; c < ATT_NC; ++c) {
        const int kb = c * 64;
        if (c + 1 < ATT_NC) load_kv((c + 1) & 1, kb + 64);
        CP_COMMIT();
        if (c + 1 < ATT_NC) { CP_WAIT1(); } else { CP_WAIT0(); }
        __syncthreads();

        const float* K = Ksm + (c & 1) * KV_TILE;
        const float* V = Vsm + (c & 1) * KV_TILE;

        const int wb = kb >> 5;
        const uint32_t mw00 = mrow0[wb], mw01 = mrow0[wb + 1];
        const uint32_t mw10 = mrow1[wb], mw11 = mrow1[wb + 1];

        float s[8][4];
#pragma unroll
        for (int nt = 0; nt < 8; ++nt) {
            s[nt][0] = s[nt][1] = s[nt][2] = s[nt][3] = 0.f;
            const float* kp = K + (nt * 8 + g) * KV_STRIDE;
#pragma unroll
            for (int ks = 0; ks < 8; ++ks) {
                uint32_t bf[2];
                bf[0] = __float_as_uint(kp[ks * 8 + t4]);
                bf[1] = __float_as_uint(kp[ks * 8 + t4 + 4]);
                mma_tf32(s[nt], aq[ks], bf);
            }
        }

        float cm0 = -INFINITY, cm1 = -INFINITY;
#pragma unroll
        for (int nt = 0; nt < 8; ++nt) {
            int colb = nt * 8 + t4 * 2;
            uint32_t wr0 = (colb < 32) ? mw00 : mw01;
            uint32_t wr1 = (colb < 32) ? mw10 : mw11;
            int sh = colb & 31;
            s[nt][0] = ((wr0 >> sh) & 1u)       ? s[nt][0] : -INFINITY;
            s[nt][1] = ((wr0 >> (sh + 1)) & 1u) ? s[nt][1] : -INFINITY;
            s[nt][2] = ((wr1 >> sh) & 1u)       ? s[nt][2] : -INFINITY;
            s[nt][3] = ((wr1 >> (sh + 1)) & 1u) ? s[nt][3] : -INFINITY;
            cm0 = fmaxf(cm0, fmaxf(s[nt][0], s[nt][1]));
            cm1 = fmaxf(cm1, fmaxf(s[nt][2], s[nt][3]));
        }
        cm0 = fmaxf(cm0, __shfl_xor_sync(0xffffffffu, cm0, 1));
        cm0 = fmaxf(cm0, __shfl_xor_sync(0xffffffffu, cm0, 2));
        cm1 = fmaxf(cm1, __shfl_xor_sync(0xffffffffu, cm1, 1));
        cm1 = fmaxf(cm1, __shfl_xor_sync(0xffffffffu, cm1, 2));

        float mn0 = fmaxf(m0, cm0), mn1 = fmaxf(m1, cm1);
        float al0 = __expf(m0 - mn0), al1 = __expf(m1 - mn1);

        float rs0 = 0.f, rs1 = 0.f;
#pragma unroll
        for (int nt = 0; nt < 8; ++nt) {
            int colb = nt * 8 + t4 * 2;
            float p0 = __expf(s[nt][0] - mn0);
            float p1 = __expf(s[nt][1] - mn0);
            float p2 = __expf(s[nt][2] - mn1);
            float p3 = __expf(s[nt][3] - mn1);
            rs0 += p0 + p1; rs1 += p2 + p3;
            *(float2*)&Ps[g * KV_STRIDE + colb]       = make_float2(p0, p1);
            *(float2*)&Ps[(8 + g) * KV_STRIDE + colb] = make_float2(p2, p3);
        }
        rs0 += __shfl_xor_sync(0xffffffffu, rs0, 1);
        rs0 += __shfl_xor_sync(0xffffffffu, rs0, 2);
        rs1 += __shfl_xor_sync(0xffffffffu, rs1, 1);
        rs1 += __shfl_xor_sync(0xffffffffu, rs1, 2);

        l0 = l0 * al0 + rs0;  m0 = mn0;
        l1 = l1 * al1 + rs1;  m1 = mn1;
#pragma unroll
        for (int nt = 0; nt < 8; ++nt) {
            o[nt][0] *= al0; o[nt][1] *= al0;
            o[nt][2] *= al1; o[nt][3] *= al1;
        }
        __syncwarp();

#pragma unroll
        for (int ks = 0; ks < 8; ++ks) {
            uint32_t ap[4];
            ap[0] = __float_as_uint(Ps[g * KV_STRIDE + ks * 8 + t4]);
            ap[1] = __float_as_uint(Ps[(8 + g) * KV_STRIDE + ks * 8 + t4]);
            ap[2] = __float_as_uint(Ps[g * KV_STRIDE + ks * 8 + t4 + 4]);
            ap[3] = __float_as_uint(Ps[(8 + g) * KV_STRIDE + ks * 8 + t4 + 4]);
            const float* vp0 = V + (ks * 8 + t4) * KV_STRIDE;
            const float* vp1 = V + (ks * 8 + t4 + 4) * KV_STRIDE;
#pragma unroll
            for (int nt = 0; nt < 8; ++nt) {
                uint32_t bf[2];
                bf[0] = __float_as_uint(vp0[nt * 8 + g]);
                bf[1] = __float_as_uint(vp1[nt * 8 + g]);
                mma_tf32(o[nt], ap, bf);
            }
        }
        __syncthreads();
    }

    {
        float inv0 = 1.0f / l0, inv1 = 1.0f / l1;
        float* ob = g_attn + ((size_t)(b * NN + qt * 128 + w * 16)) * CC + h * DH;
#pragma unroll
        for (int nt = 0; nt < 8; ++nt) {
            int col = nt * 8 + t4 * 2;
            *(float2*)(ob + (size_t)g * CC + col) =
                make_float2(o[nt][0] * inv0, o[nt][1] * inv0);
            *(float2*)(ob + (size_t)(8 + g) * CC + col) =
                make_float2(o[nt][2] * inv1, o[nt][3] * inv1);
        }
    }
}

// ---------------------------------------------------------------------------
// Launch
// ---------------------------------------------------------------------------
extern "C" void kernel_launch(void* const* d_in, const int* in_sizes, int n_in,
                              void* d_out, int out_size) {
    const float* x     = (const float*)d_in[0];
    const float* ce    = (const float*)d_in[1];
    const int*   mask  = (const int*)  d_in[2];
    const float* ln1_g = (const float*)d_in[3];
    const float* ln1_b = (const float*)d_in[4];
    const float* ln2_g = (const float*)d_in[5];
    const float* ln2_b = (const float*)d_in[6];
    const float* Wq = (const float*)d_in[7];
    const float* bq = (const float*)d_in[8];
    const float* Wk = (const float*)d_in[9];
    const float* bk = (const float*)d_in[10];
    const float* Wv = (const float*)d_in[11];
    const float* bv = (const float*)d_in[12];
    const float* Wp = (const float*)d_in[13];
    const float* bp = (const float*)d_in[14];
    const float* W1 = (const float*)d_in[15];
    const float* b1 = (const float*)d_in[16];
    const float* W2 = (const float*)d_in[17];
    const float* b2 = (const float*)d_in[18];
    float* out = (float*)d_out;

    cudaFuncSetAttribute(gemm_tc<0>, cudaFuncAttributeMaxDynamicSharedMemorySize, GEMM_SMEM);
    cudaFuncSetAttribute(gemm_tc<1>, cudaFuncAttributeMaxDynamicSharedMemorySize, GEMM_SMEM);
    cudaFuncSetAttribute(gemm_tc<2>, cudaFuncAttributeMaxDynamicSharedMemorySize, GEMM_SMEM);
    cudaFuncSetAttribute(attn_tc,    cudaFuncAttributeMaxDynamicSharedMemorySize, ATT_SMEM);

    float *p_xn, *p_tokens, *p_q, *p_k, *p_v, *p_attn, *p_x1, *p_h, *p_mlp;
    uint32_t* p_mbits;
    cudaGetSymbolAddress((void**)&p_xn,     g_xn);
    cudaGetSymbolAddress((void**)&p_tokens, g_tokens);
    cudaGetSymbolAddress((void**)&p_q,      g_q);
    cudaGetSymbolAddress((void**)&p_k,      g_k);
    cudaGetSymbolAddress((void**)&p_v,      g_v);
    cudaGetSymbolAddress((void**)&p_attn,   g_attn);
    cudaGetSymbolAddress((void**)&p_x1,     g_x1);
    cudaGetSymbolAddress((void**)&p_h,      g_h);
    cudaGetSymbolAddress((void**)&p_mlp,    g_mlp);
    cudaGetSymbolAddress((void**)&p_mbits,  g_mbits);

    const int Mq = BB * NN;     // 16384
    const int Mt = BB * NL;     // 21392
    const int MqT = (Mq + 127) / 128;
    const int MtT = (Mt + 127) / 128;

    // 1) LN1 -> xn (+ head of tokens); pack mask bits
    ln_kernel<<<Mq, 256>>>(x, ln1_g, ln1_b, p_xn, 1);
    {
        int totalw = BB * NN * MW;
        pack_mask_kernel<<<(totalw + 255) / 256, 256>>>(mask);
    }
    // 2) tokens tail <- color_emb
    {
        int total = BB * LL * CC;
        copy_color_kernel<<<(total + 255) / 256, 256>>>(ce);
    }
    // 3) Q = xn @ Wq + bq
    gemm_tc<0><<<dim3(CC / 128, MqT), 256, GEMM_SMEM>>>(p_xn, Wq, bq, nullptr, p_q, Mq, CC, CC);
    // 4) K = tokens @ Wk + bk
    gemm_tc<0><<<dim3(CC / 128, MtT), 256, GEMM_SMEM>>>(p_tokens, Wk, bk, nullptr, p_k, Mt, CC, CC);
    // 5) V = tokens @ Wv + bv
    gemm_tc<0><<<dim3(CC / 128, MtT), 256, GEMM_SMEM>>>(p_tokens, Wv, bv, nullptr, p_v, Mt, CC, CC);
    // 6) tensor-core flash attention -> g_attn
    attn_tc<<<dim3(NN / 128, HH, BB), 256, ATT_SMEM>>>(p_mbits);
    // 7) x1 = xn + (attn @ Wp + bp)
    gemm_tc<1><<<dim3(CC / 128, MqT), 256, GEMM_SMEM>>>(p_attn, Wp, bp, p_xn, p_x1, Mq, CC, CC);
    // 8) h = LN2(x1)
    ln_kernel<<<Mq, 256>>>(p_x1, ln2_g, ln2_b, p_h, 0);
    // 9) mlp = gelu(h @ W1 + b1)
    gemm_tc<2><<<dim3(MLPD / 128, MqT), 256, GEMM_SMEM>>>(p_h, W1, b1, nullptr, p_mlp, Mq, CC, MLPD);
    // 10) out = x1 + (mlp @ W2 + b2)
    gemm_tc<1><<<dim3(CC / 128, MqT), 256, GEMM_SMEM>>>(p_mlp, W2, b2, p_x1, out, Mq, MLPD, CC);
}